// round 1
// baseline (speedup 1.0000x reference)
#include <cuda_runtime.h>
#include <cuda_bf16.h>
#include <math.h>
#include <stdint.h>

// Problem constants
#define BB 2
#define SS 2048
#define DD 1024
#define HH 16
#define DH 64
#define BH (BB*HH)          // 32
#define MROWS (BB*SS)       // 4096

// Scratch (device globals: allocation-free)
__device__ float g_Q[BH * SS * DH];    // [B,H,S,DH] 16MB
__device__ float g_K[BH * SS * DH];
__device__ float g_V[BH * SS * DH];
__device__ float g_Ctx[MROWS * DD];    // [B,S,D] merged heads

// ---------------------------------------------------------------------------
// Generic tiled fp32 GEMM: C = A * B^T (+ epilogue), A[M,K] rm, B[N,K] rm.
// BM=BN=128, BK=16, 256 threads, 8x8 microtile.
// MODE 0: proj   (bias add, scatter to head-split [B,H,S,DH])
// MODE 1: dense  (bias add, row-major out)
// MODE 2: scores (scale + mask -> -inf, per-z head offsets, out = weights)
// ---------------------------------------------------------------------------
#define GBM 128
#define GBN 128
#define GBK 16

template<int MODE>
__global__ __launch_bounds__(256)
void gemm_kernel(const float* __restrict__ Aall, const float* __restrict__ Ball,
                 const void* __restrict__ aux, float* __restrict__ Call,
                 int M, int N, int K)
{
    __shared__ float As[GBK][GBM + 4];
    __shared__ float Bs[GBK][GBN + 4];

    const int tid = threadIdx.x;
    const float* A = Aall;
    const float* Bw = Ball;
    float* C = Call;
    const int* mask = nullptr;
    const float* bias = nullptr;

    if (MODE == 2) {
        const int z = blockIdx.z;  // b*H + h
        A = Aall + (size_t)z * SS * DH;
        Bw = Ball + (size_t)z * SS * DH;
        C = Call + (size_t)z * SS * SS;
        mask = ((const int*)aux) + (size_t)(z / HH) * SS * SS;
    } else {
        bias = (const float*)aux;
    }

    const int row0 = blockIdx.y * GBM;
    const int col0 = blockIdx.x * GBN;
    const int ty = tid >> 4;    // 0..15
    const int tx = tid & 15;    // 0..15

    float acc[8][8];
    #pragma unroll
    for (int i = 0; i < 8; ++i)
        #pragma unroll
        for (int j = 0; j < 8; ++j) acc[i][j] = 0.0f;

    for (int kt = 0; kt < K; kt += GBK) {
        // Load A tile (128x16) and B tile (128x16), transposed into smem.
        int idx = tid;
        #pragma unroll
        for (int it = 0; it < 2; ++it, idx += 256) {
            const int r  = idx >> 2;          // 0..127
            const int c4 = (idx & 3) * 4;     // 0,4,8,12
            float4 va = *(const float4*)&A[(size_t)(row0 + r) * K + kt + c4];
            As[c4+0][r] = va.x; As[c4+1][r] = va.y;
            As[c4+2][r] = va.z; As[c4+3][r] = va.w;
            float4 vb = *(const float4*)&Bw[(size_t)(col0 + r) * K + kt + c4];
            Bs[c4+0][r] = vb.x; Bs[c4+1][r] = vb.y;
            Bs[c4+2][r] = vb.z; Bs[c4+3][r] = vb.w;
        }
        __syncthreads();

        #pragma unroll
        for (int k = 0; k < GBK; ++k) {
            float4 a0 = *(const float4*)&As[k][ty * 8];
            float4 a1 = *(const float4*)&As[k][ty * 8 + 4];
            float4 b0 = *(const float4*)&Bs[k][tx * 8];
            float4 b1 = *(const float4*)&Bs[k][tx * 8 + 4];
            float a[8] = {a0.x, a0.y, a0.z, a0.w, a1.x, a1.y, a1.z, a1.w};
            float b[8] = {b0.x, b0.y, b0.z, b0.w, b1.x, b1.y, b1.z, b1.w};
            #pragma unroll
            for (int i = 0; i < 8; ++i)
                #pragma unroll
                for (int j = 0; j < 8; ++j)
                    acc[i][j] = fmaf(a[i], b[j], acc[i][j]);
        }
        __syncthreads();
    }

    // Epilogue
    if (MODE == 0) {
        #pragma unroll
        for (int i = 0; i < 8; ++i) {
            const int gr = row0 + ty * 8 + i;
            const int b = gr / SS, s = gr % SS;
            #pragma unroll
            for (int j = 0; j < 8; ++j) {
                const int gc = col0 + tx * 8 + j;
                const int h = gc >> 6, d = gc & 63;
                C[(((size_t)(b * HH + h)) * SS + s) * DH + d] = acc[i][j] + bias[gc];
            }
        }
    } else if (MODE == 1) {
        #pragma unroll
        for (int i = 0; i < 8; ++i) {
            const int gr = row0 + ty * 8 + i;
            #pragma unroll
            for (int j = 0; j < 8; ++j) {
                const int gc = col0 + tx * 8 + j;
                C[(size_t)gr * N + gc] = acc[i][j] + bias[gc];
            }
        }
    } else {
        const float scale = 0.125f;   // 1/sqrt(64)
        #pragma unroll
        for (int i = 0; i < 8; ++i) {
            const int gr = row0 + ty * 8 + i;
            #pragma unroll
            for (int j = 0; j < 8; ++j) {
                const int gc = col0 + tx * 8 + j;
                const int mv = mask[(size_t)gr * SS + gc];
                C[(size_t)gr * SS + gc] = mv ? acc[i][j] * scale : -INFINITY;
            }
        }
    }
}

// ---------------------------------------------------------------------------
// Row softmax in place: 65536 rows of 2048 fp32 (one block per row).
// ---------------------------------------------------------------------------
__global__ __launch_bounds__(256)
void softmax_kernel(float* __restrict__ Wt)
{
    __shared__ float red[8];
    const size_t row = blockIdx.x;
    float4* rp = ((float4*)Wt) + row * (SS / 4);
    const int tid = threadIdx.x;

    float4 v0 = rp[tid];
    float4 v1 = rp[tid + 256];

    float m = fmaxf(fmaxf(fmaxf(v0.x, v0.y), fmaxf(v0.z, v0.w)),
                    fmaxf(fmaxf(v1.x, v1.y), fmaxf(v1.z, v1.w)));
    #pragma unroll
    for (int o = 16; o; o >>= 1) m = fmaxf(m, __shfl_xor_sync(0xffffffffu, m, o));
    if ((tid & 31) == 0) red[tid >> 5] = m;
    __syncthreads();
    m = red[0];
    #pragma unroll
    for (int i = 1; i < 8; ++i) m = fmaxf(m, red[i]);
    __syncthreads();

    float e[8];
    e[0] = expf(v0.x - m); e[1] = expf(v0.y - m);
    e[2] = expf(v0.z - m); e[3] = expf(v0.w - m);
    e[4] = expf(v1.x - m); e[5] = expf(v1.y - m);
    e[6] = expf(v1.z - m); e[7] = expf(v1.w - m);

    float s = 0.0f;
    #pragma unroll
    for (int i = 0; i < 8; ++i) s += e[i];
    #pragma unroll
    for (int o = 16; o; o >>= 1) s += __shfl_xor_sync(0xffffffffu, s, o);
    if ((tid & 31) == 0) red[tid >> 5] = s;
    __syncthreads();
    float l = red[0];
    #pragma unroll
    for (int i = 1; i < 8; ++i) l += red[i];

    const float inv = 1.0f / l;
    rp[tid]       = make_float4(e[0] * inv, e[1] * inv, e[2] * inv, e[3] * inv);
    rp[tid + 256] = make_float4(e[4] * inv, e[5] * inv, e[6] * inv, e[7] * inv);
}

// ---------------------------------------------------------------------------
// AV GEMM: per (b,h): C[2048,64] = W[2048,2048] * V[2048,64]
// BM=64, BN=64, BK=32, 256 threads, 4x4 microtile. Output merged-head Ctx.
// ---------------------------------------------------------------------------
__global__ __launch_bounds__(256)
void av_kernel(const float* __restrict__ Wts, const float* __restrict__ Vh,
               float* __restrict__ Ctx)
{
    __shared__ float As[32][68];
    __shared__ float Bs[32][68];

    const int z = blockIdx.y;                 // b*H + h
    const float* Aw = Wts + (size_t)z * SS * SS;
    const float* Vv = Vh + (size_t)z * SS * DH;
    const int row0 = blockIdx.x * 64;
    const int tid = threadIdx.x;
    const int ty = tid >> 4, tx = tid & 15;

    float acc[4][4];
    #pragma unroll
    for (int i = 0; i < 4; ++i)
        #pragma unroll
        for (int j = 0; j < 4; ++j) acc[i][j] = 0.0f;

    for (int kt = 0; kt < SS; kt += 32) {
        // A tile 64x32 transposed
        int idx = tid;
        #pragma unroll
        for (int it = 0; it < 2; ++it, idx += 256) {
            const int r  = idx >> 3;          // 0..63
            const int c4 = (idx & 7) * 4;     // 0..28
            float4 v = *(const float4*)&Aw[(size_t)(row0 + r) * SS + kt + c4];
            As[c4+0][r] = v.x; As[c4+1][r] = v.y;
            As[c4+2][r] = v.z; As[c4+3][r] = v.w;
        }
        // B tile 32x64 direct
        idx = tid;
        #pragma unroll
        for (int it = 0; it < 2; ++it, idx += 256) {
            const int r  = idx >> 4;          // 0..31
            const int c4 = (idx & 15) * 4;    // 0..60
            float4 v = *(const float4*)&Vv[(size_t)(kt + r) * DH + c4];
            *(float4*)&Bs[r][c4] = v;
        }
        __syncthreads();

        #pragma unroll
        for (int k = 0; k < 32; ++k) {
            float4 a = *(const float4*)&As[k][ty * 4];
            float4 b = *(const float4*)&Bs[k][tx * 4];
            float av[4] = {a.x, a.y, a.z, a.w};
            float bv[4] = {b.x, b.y, b.z, b.w};
            #pragma unroll
            for (int i = 0; i < 4; ++i)
                #pragma unroll
                for (int j = 0; j < 4; ++j)
                    acc[i][j] = fmaf(av[i], bv[j], acc[i][j]);
        }
        __syncthreads();
    }

    const int b = z / HH, h = z % HH;
    #pragma unroll
    for (int i = 0; i < 4; ++i) {
        const int s = row0 + ty * 4 + i;
        float4 v = make_float4(acc[i][0], acc[i][1], acc[i][2], acc[i][3]);
        *(float4*)&Ctx[((size_t)(b * SS + s)) * DD + h * 64 + tx * 4] = v;
    }
}

// ---------------------------------------------------------------------------
// kernel_launch
// ---------------------------------------------------------------------------
extern "C" void kernel_launch(void* const* d_in, const int* in_sizes, int n_in,
                              void* d_out, int out_size)
{
    const float* q       = (const float*)d_in[0];
    const float* k       = (const float*)d_in[1];
    const float* v       = (const float*)d_in[2];
    const int*   mask    = (const int*)d_in[3];
    const float* wq_w    = (const float*)d_in[4];
    const float* wq_b    = (const float*)d_in[5];
    const float* wk_w    = (const float*)d_in[6];
    const float* wk_b    = (const float*)d_in[7];
    const float* wv_w    = (const float*)d_in[8];
    const float* wv_b    = (const float*)d_in[9];
    const float* dense_w = (const float*)d_in[10];
    const float* dense_b = (const float*)d_in[11];

    float* out = (float*)d_out;                       // [B,S,D]
    float* wts = out + (size_t)BB * SS * DD;          // [B,H,S,S]

    void *pQ, *pK, *pV, *pC;
    cudaGetSymbolAddress(&pQ, g_Q);
    cudaGetSymbolAddress(&pK, g_K);
    cudaGetSymbolAddress(&pV, g_V);
    cudaGetSymbolAddress(&pC, g_Ctx);
    float* gQ = (float*)pQ;
    float* gK = (float*)pK;
    float* gV = (float*)pV;
    float* gC = (float*)pC;

    const dim3 blk(256);

    // 1) QKV projections: [4096,1024] = X @ W^T + b -> head-split layout
    const dim3 gproj(DD / GBN, MROWS / GBM, 1);       // (8, 32)
    gemm_kernel<0><<<gproj, blk>>>(q, wq_w, (const void*)wq_b, gQ, MROWS, DD, DD);
    gemm_kernel<0><<<gproj, blk>>>(k, wk_w, (const void*)wk_b, gK, MROWS, DD, DD);
    gemm_kernel<0><<<gproj, blk>>>(v, wv_w, (const void*)wv_b, gV, MROWS, DD, DD);

    // 2) Scores: per (b,h): Q @ K^T * scale, mask -> weights region (raw)
    const dim3 gsc(SS / GBN, SS / GBM, BH);           // (16, 16, 32)
    gemm_kernel<2><<<gsc, blk>>>(gQ, gK, (const void*)mask, wts, SS, SS, DH);

    // 3) Softmax in place over weights rows
    softmax_kernel<<<BH * SS, 256>>>(wts);

    // 4) AV: per (b,h): W @ V -> merged-head Ctx
    const dim3 gav(SS / 64, BH, 1);                   // (32, 32)
    av_kernel<<<gav, blk>>>(wts, gV, gC);

    // 5) Dense: Ctx @ dense_w^T + b -> out
    gemm_kernel<1><<<gproj, blk>>>(gC, dense_w, (const void*)dense_b, out, MROWS, DD, DD);
}

// round 2
// speedup vs baseline: 2.1952x; 2.1952x over previous
#include <cuda_runtime.h>
#include <cuda_bf16.h>
#include <math.h>
#include <stdint.h>

#define BB 2
#define SS 2048
#define DD 1024
#define HH 16
#define DH 64
#define BH (BB*HH)          // 32
#define MROWS (BB*SS)       // 4096

// Scratch (device globals: allocation-free)
__device__ float g_Q[BH * SS * DH];    // [B,H,S,DH]
__device__ float g_K[BH * SS * DH];
__device__ float g_V[BH * SS * DH];
__device__ float g_Ctx[MROWS * DD];    // [B,S,D] merged heads

__device__ __forceinline__ float to_tf32(float x) {
    uint32_t u;
    asm("cvt.rna.tf32.f32 %0, %1;" : "=r"(u) : "f"(x));
    return __uint_as_float(u);
}

#define MMA_TF32(c, a, b)                                                     \
    asm volatile(                                                             \
        "mma.sync.aligned.m16n8k8.row.col.f32.tf32.tf32.f32 "                 \
        "{%0,%1,%2,%3},{%4,%5,%6,%7},{%8,%9},{%0,%1,%2,%3};\n"                \
        : "+f"(c[0]), "+f"(c[1]), "+f"(c[2]), "+f"(c[3])                      \
        : "r"(a[0]), "r"(a[1]), "r"(a[2]), "r"(a[3]), "r"(b[0]), "r"(b[1]))

// ---------------------------------------------------------------------------
// TF32 MMA GEMM: C = A * B^T (+epilogue). A[M,K] rm, B[N,K] rm.
// BM=BN=128, BK=32, 256 threads (8 warps, 2x4), warp tile 64x32.
// MODE 0: proj (bias, scatter to [B,H,S,DH])
// MODE 1: dense (bias, row-major)
// MODE 2: scores (scale+mask, per-z offsets)
// ---------------------------------------------------------------------------
template<int MODE>
__global__ __launch_bounds__(256)
void mma_nt(const float* __restrict__ Aall, const float* __restrict__ Ball,
            const void* __restrict__ aux, float* __restrict__ Call, int K)
{
    __shared__ float As[128][36];
    __shared__ float Bs[128][36];

    const int tid = threadIdx.x;
    const int wid = tid >> 5, lane = tid & 31;
    const int g = lane >> 2, q = lane & 3;
    const int wm0 = (wid >> 2) * 64;
    const int wn0 = (wid & 3) * 32;
    const int row0 = blockIdx.y * 128;
    const int col0 = blockIdx.x * 128;

    const float* A = Aall;
    const float* Bw = Ball;
    float* C = Call;
    const int* mask = nullptr;
    const float* bias = nullptr;
    if (MODE == 2) {
        const int z = blockIdx.z;
        A  = Aall + (size_t)z * SS * DH;
        Bw = Ball + (size_t)z * SS * DH;
        C  = Call + (size_t)z * SS * SS;
        mask = ((const int*)aux) + (size_t)(z / HH) * SS * SS;
    } else {
        bias = (const float*)aux;
    }

    float acc[4][4][4];
    #pragma unroll
    for (int i = 0; i < 4; ++i)
        #pragma unroll
        for (int j = 0; j < 4; ++j)
            #pragma unroll
            for (int r = 0; r < 4; ++r) acc[i][j][r] = 0.0f;

    for (int kt = 0; kt < K; kt += 32) {
        #pragma unroll
        for (int it = 0; it < 4; ++it) {
            const int idx = tid + it * 256;
            const int r = idx >> 3;
            const int c4 = (idx & 7) << 2;
            float4 va = *(const float4*)&A[(size_t)(row0 + r) * K + kt + c4];
            *(float4*)&As[r][c4] = make_float4(to_tf32(va.x), to_tf32(va.y),
                                               to_tf32(va.z), to_tf32(va.w));
            float4 vb = *(const float4*)&Bw[(size_t)(col0 + r) * K + kt + c4];
            *(float4*)&Bs[r][c4] = make_float4(to_tf32(vb.x), to_tf32(vb.y),
                                               to_tf32(vb.z), to_tf32(vb.w));
        }
        __syncthreads();

        #pragma unroll
        for (int kk = 0; kk < 4; ++kk) {
            const int kb = kk * 8;
            uint32_t a[4][4], b[4][2];
            #pragma unroll
            for (int i = 0; i < 4; ++i) {
                a[i][0] = __float_as_uint(As[wm0 + 16*i + g    ][kb + q    ]);
                a[i][1] = __float_as_uint(As[wm0 + 16*i + g + 8][kb + q    ]);
                a[i][2] = __float_as_uint(As[wm0 + 16*i + g    ][kb + q + 4]);
                a[i][3] = __float_as_uint(As[wm0 + 16*i + g + 8][kb + q + 4]);
            }
            #pragma unroll
            for (int j = 0; j < 4; ++j) {
                b[j][0] = __float_as_uint(Bs[wn0 + 8*j + g][kb + q    ]);
                b[j][1] = __float_as_uint(Bs[wn0 + 8*j + g][kb + q + 4]);
            }
            #pragma unroll
            for (int i = 0; i < 4; ++i)
                #pragma unroll
                for (int j = 0; j < 4; ++j)
                    MMA_TF32(acc[i][j], a[i], b[j]);
        }
        __syncthreads();
    }

    // Epilogue: c0,c1 at (row, 2q..2q+1); c2,c3 at (row+8, same cols)
    #pragma unroll
    for (int i = 0; i < 4; ++i) {
        #pragma unroll
        for (int rr = 0; rr < 2; ++rr) {
            const int gr = row0 + wm0 + 16*i + g + rr*8;
            #pragma unroll
            for (int j = 0; j < 4; ++j) {
                const int gc = col0 + wn0 + 8*j + 2*q;
                const float v0 = acc[i][j][rr*2 + 0];
                const float v1 = acc[i][j][rr*2 + 1];
                if (MODE == 0) {
                    const int b = gr >> 11, s = gr & 2047;
                    const int h = gc >> 6, d = gc & 63;
                    float2 bv = *(const float2*)&bias[gc];
                    *(float2*)&C[(((size_t)(b*HH + h))*SS + s)*DH + d] =
                        make_float2(v0 + bv.x, v1 + bv.y);
                } else if (MODE == 1) {
                    float2 bv = *(const float2*)&bias[gc];
                    *(float2*)&C[(size_t)gr * DD + gc] =
                        make_float2(v0 + bv.x, v1 + bv.y);
                } else {
                    int2 mv = *(const int2*)&mask[(size_t)gr * SS + gc];
                    *(float2*)&C[(size_t)gr * SS + gc] = make_float2(
                        mv.x ? v0 * 0.125f : -INFINITY,
                        mv.y ? v1 * 0.125f : -INFINITY);
                }
            }
        }
    }
}

// ---------------------------------------------------------------------------
// Row softmax in place: BH*S rows of 2048 fp32 (one block per row).
// ---------------------------------------------------------------------------
__global__ __launch_bounds__(256)
void softmax_kernel(float* __restrict__ Wt)
{
    __shared__ float red[8];
    const size_t row = blockIdx.x;
    float4* rp = ((float4*)Wt) + row * (SS / 4);
    const int tid = threadIdx.x;

    float4 v0 = rp[tid];
    float4 v1 = rp[tid + 256];

    float m = fmaxf(fmaxf(fmaxf(v0.x, v0.y), fmaxf(v0.z, v0.w)),
                    fmaxf(fmaxf(v1.x, v1.y), fmaxf(v1.z, v1.w)));
    #pragma unroll
    for (int o = 16; o; o >>= 1) m = fmaxf(m, __shfl_xor_sync(0xffffffffu, m, o));
    if ((tid & 31) == 0) red[tid >> 5] = m;
    __syncthreads();
    m = red[0];
    #pragma unroll
    for (int i = 1; i < 8; ++i) m = fmaxf(m, red[i]);
    __syncthreads();

    float e[8];
    e[0] = expf(v0.x - m); e[1] = expf(v0.y - m);
    e[2] = expf(v0.z - m); e[3] = expf(v0.w - m);
    e[4] = expf(v1.x - m); e[5] = expf(v1.y - m);
    e[6] = expf(v1.z - m); e[7] = expf(v1.w - m);

    float s = 0.0f;
    #pragma unroll
    for (int i = 0; i < 8; ++i) s += e[i];
    #pragma unroll
    for (int o = 16; o; o >>= 1) s += __shfl_xor_sync(0xffffffffu, s, o);
    if ((tid & 31) == 0) red[tid >> 5] = s;
    __syncthreads();
    float l = red[0];
    #pragma unroll
    for (int i = 1; i < 8; ++i) l += red[i];

    const float inv = 1.0f / l;
    rp[tid]       = make_float4(e[0]*inv, e[1]*inv, e[2]*inv, e[3]*inv);
    rp[tid + 256] = make_float4(e[4]*inv, e[5]*inv, e[6]*inv, e[7]*inv);
}

// ---------------------------------------------------------------------------
// AV GEMM (nn): per z: C[2048,64] = W[2048,2048] * V[2048,64], tf32 MMA.
// BM=128, BN=64, BK=32, 8 warps (4x2), warp tile 32x32.
// ---------------------------------------------------------------------------
__global__ __launch_bounds__(256)
void mma_av(const float* __restrict__ Wts, const float* __restrict__ Vh,
            float* __restrict__ Ctx)
{
    __shared__ float As[128][36];
    __shared__ float Bs[32][68];

    const int z = blockIdx.y;
    const float* Aw = Wts + (size_t)z * SS * SS;
    const float* Vv = Vh  + (size_t)z * SS * DH;
    const int row0 = blockIdx.x * 128;

    const int tid = threadIdx.x;
    const int wid = tid >> 5, lane = tid & 31;
    const int g = lane >> 2, q = lane & 3;
    const int wm0 = (wid >> 1) * 32;
    const int wn0 = (wid & 1) * 32;

    float acc[2][4][4];
    #pragma unroll
    for (int i = 0; i < 2; ++i)
        #pragma unroll
        for (int j = 0; j < 4; ++j)
            #pragma unroll
            for (int r = 0; r < 4; ++r) acc[i][j][r] = 0.0f;

    for (int kt = 0; kt < SS; kt += 32) {
        #pragma unroll
        for (int it = 0; it < 4; ++it) {
            const int idx = tid + it * 256;
            const int r = idx >> 3;
            const int c4 = (idx & 7) << 2;
            float4 v = *(const float4*)&Aw[(size_t)(row0 + r) * SS + kt + c4];
            *(float4*)&As[r][c4] = make_float4(to_tf32(v.x), to_tf32(v.y),
                                               to_tf32(v.z), to_tf32(v.w));
        }
        #pragma unroll
        for (int it = 0; it < 2; ++it) {
            const int idx = tid + it * 256;
            const int r = idx >> 4;
            const int c4 = (idx & 15) << 2;
            float4 v = *(const float4*)&Vv[(size_t)(kt + r) * DH + c4];
            *(float4*)&Bs[r][c4] = make_float4(to_tf32(v.x), to_tf32(v.y),
                                               to_tf32(v.z), to_tf32(v.w));
        }
        __syncthreads();

        #pragma unroll
        for (int kk = 0; kk < 4; ++kk) {
            const int kb = kk * 8;
            uint32_t a[2][4], b[4][2];
            #pragma unroll
            for (int i = 0; i < 2; ++i) {
                a[i][0] = __float_as_uint(As[wm0 + 16*i + g    ][kb + q    ]);
                a[i][1] = __float_as_uint(As[wm0 + 16*i + g + 8][kb + q    ]);
                a[i][2] = __float_as_uint(As[wm0 + 16*i + g    ][kb + q + 4]);
                a[i][3] = __float_as_uint(As[wm0 + 16*i + g + 8][kb + q + 4]);
            }
            #pragma unroll
            for (int j = 0; j < 4; ++j) {
                b[j][0] = __float_as_uint(Bs[kb + q    ][wn0 + 8*j + g]);
                b[j][1] = __float_as_uint(Bs[kb + q + 4][wn0 + 8*j + g]);
            }
            #pragma unroll
            for (int i = 0; i < 2; ++i)
                #pragma unroll
                for (int j = 0; j < 4; ++j)
                    MMA_TF32(acc[i][j], a[i], b[j]);
        }
        __syncthreads();
    }

    const int b = z / HH, h = z % HH;
    #pragma unroll
    for (int i = 0; i < 2; ++i) {
        #pragma unroll
        for (int rr = 0; rr < 2; ++rr) {
            const int s = row0 + wm0 + 16*i + g + rr*8;
            #pragma unroll
            for (int j = 0; j < 4; ++j) {
                const int n = wn0 + 8*j + 2*q;
                *(float2*)&Ctx[((size_t)(b*SS + s))*DD + h*64 + n] =
                    make_float2(acc[i][j][rr*2], acc[i][j][rr*2 + 1]);
            }
        }
    }
}

// ---------------------------------------------------------------------------
extern "C" void kernel_launch(void* const* d_in, const int* in_sizes, int n_in,
                              void* d_out, int out_size)
{
    const float* q       = (const float*)d_in[0];
    const float* k       = (const float*)d_in[1];
    const float* v       = (const float*)d_in[2];
    const int*   mask    = (const int*)d_in[3];
    const float* wq_w    = (const float*)d_in[4];
    const float* wq_b    = (const float*)d_in[5];
    const float* wk_w    = (const float*)d_in[6];
    const float* wk_b    = (const float*)d_in[7];
    const float* wv_w    = (const float*)d_in[8];
    const float* wv_b    = (const float*)d_in[9];
    const float* dense_w = (const float*)d_in[10];
    const float* dense_b = (const float*)d_in[11];

    float* out = (float*)d_out;                       // [B,S,D]
    float* wts = out + (size_t)BB * SS * DD;          // [B,H,S,S]

    void *pQ, *pK, *pV, *pC;
    cudaGetSymbolAddress(&pQ, g_Q);
    cudaGetSymbolAddress(&pK, g_K);
    cudaGetSymbolAddress(&pV, g_V);
    cudaGetSymbolAddress(&pC, g_Ctx);
    float* gQ = (float*)pQ;
    float* gK = (float*)pK;
    float* gV = (float*)pV;
    float* gC = (float*)pC;

    const dim3 blk(256);

    // 1) QKV projections -> head-split layout
    const dim3 gproj(DD / 128, MROWS / 128, 1);       // (8, 32)
    mma_nt<0><<<gproj, blk>>>(q, wq_w, (const void*)wq_b, gQ, DD);
    mma_nt<0><<<gproj, blk>>>(k, wk_w, (const void*)wk_b, gK, DD);
    mma_nt<0><<<gproj, blk>>>(v, wv_w, (const void*)wv_b, gV, DD);

    // 2) Scores -> weights region (raw, masked, scaled)
    const dim3 gsc(SS / 128, SS / 128, BH);           // (16, 16, 32)
    mma_nt<2><<<gsc, blk>>>(gQ, gK, (const void*)mask, wts, DH);

    // 3) Softmax in place
    softmax_kernel<<<BH * SS, 256>>>(wts);

    // 4) AV -> merged-head Ctx
    const dim3 gav(SS / 128, BH, 1);                  // (16, 32)
    mma_av<<<gav, blk>>>(wts, gV, gC);

    // 5) Dense -> out
    mma_nt<1><<<gproj, blk>>>(gC, dense_w, (const void*)dense_b, out, DD);
}